// round 14
// baseline (speedup 1.0000x reference)
#include <cuda_runtime.h>
#include <cstdint>

// ============================================================================
// LoRADense: out = x @ W + bias + (x . A[id]) . B[id]
//   x:(8192,1024)f32  ids:(8192,)i32  W:(1024,1024)f32  bias:(1024,)f32
//   lora_a:(64,1024,16)f32  lora_b:(64,16,1024)f32
//
// R14 = R12 resubmit (two infra failures):
//   L1: rv = x.A[id], 1 token/warp (~70 regs, no spills at occ 2),
//       A^T smem conflict-free, butterfly reduce
//   GEMM: cp.async mma.sync tf32 (at its HMMA floor ~65us)
//   L2: token-major streaming out += rv.B[id] (34.7us measured)
// ============================================================================

#define N_TOK 8192
#define DIM   1024
#define FEAT  1024

__device__ float g_wt[FEAT * DIM];     // W^T tf32-rounded (4 MB)
__device__ float g_rv[N_TOK * 16];     // low-rank intermediate (512 KB)

__device__ __forceinline__ uint32_t to_tf32(float v) {
    uint32_t o;
    asm("cvt.rna.tf32.f32 %0, %1;" : "=r"(o) : "f"(v));
    return o;
}
__device__ __forceinline__ void cp16(uint32_t dst, const void* src) {
    asm volatile("cp.async.cg.shared.global [%0], [%1], 16;" :: "r"(dst), "l"(src));
}
__device__ __forceinline__ uint32_t smem_u32(const void* p) {
    uint32_t a;
    asm("{ .reg .u64 t; cvta.to.shared.u64 t, %1; cvt.u32.u64 %0, t; }"
        : "=r"(a) : "l"(p));
    return a;
}
__device__ __forceinline__ void mma_tf32(float& c0, float& c1, float& c2, float& c3,
                                         uint32_t a0, uint32_t a1, uint32_t a2, uint32_t a3,
                                         uint32_t b0, uint32_t b1) {
    asm volatile(
        "mma.sync.aligned.m16n8k8.row.col.f32.tf32.tf32.f32 "
        "{%0,%1,%2,%3}, {%4,%5,%6,%7}, {%8,%9}, {%0,%1,%2,%3};"
        : "+f"(c0), "+f"(c1), "+f"(c2), "+f"(c3)
        : "r"(a0), "r"(a1), "r"(a2), "r"(a3), "r"(b0), "r"(b1));
}

// ============================================================================
// Kernel 1: W (D,F) -> g_wt (F,D), tf32-rounded
// ============================================================================
__global__ void transpose_w_kernel(const float* __restrict__ W) {
    __shared__ float t[32][33];
    int fx = blockIdx.x * 32 + threadIdx.x;
    int dy = blockIdx.y * 32 + threadIdx.y;
#pragma unroll
    for (int i = 0; i < 32; i += 8)
        t[threadIdx.y + i][threadIdx.x] = W[(size_t)(dy + i) * FEAT + fx];
    __syncthreads();
    int dx = blockIdx.y * 32 + threadIdx.x;
    int fy = blockIdx.x * 32 + threadIdx.y;
#pragma unroll
    for (int i = 0; i < 32; i += 8)
        g_wt[(size_t)(fy + i) * DIM + dx] =
            __uint_as_float(to_tf32(t[threadIdx.x][threadIdx.y + i]));
}

// ============================================================================
// Kernel 2: tf32 GEMM, BM=256 BN=128 BK=32, 256 thr, 64x64 warp tiles
// ============================================================================
static constexpr int BM = 256, BN = 128, BK = 32;
static constexpr int AS = 36;
static constexpr int NKCH = DIM / BK;
static constexpr int DEPTH = 3;
static constexpr int A_FLOATS = BM * AS;
static constexpr int B_FLOATS = BN * AS;
static constexpr int STAGE_FLOATS = A_FLOATS + B_FLOATS;
static constexpr int GEMM_SMEM = DEPTH * STAGE_FLOATS * 4;   // 165888 B

__device__ __forceinline__ void load_stage(uint32_t sb, int slot, int kc,
                                           const float* __restrict__ x,
                                           int mbase, int nbase, int tid) {
    uint32_t baseA = sb + (uint32_t)(slot * STAGE_FLOATS) * 4u;
    uint32_t baseB = baseA + (uint32_t)A_FLOATS * 4u;
    const float* xp = x    + (size_t)mbase * DIM + kc * BK;
    const float* wp = g_wt + (size_t)nbase * DIM + kc * BK;
#pragma unroll
    for (int it = 0; it < 8; it++) {
        int c  = tid + it * 256;
        int r  = c >> 3, cc = c & 7;
        cp16(baseA + (uint32_t)(r * AS + cc * 4) * 4u, xp + (size_t)r * DIM + cc * 4);
    }
#pragma unroll
    for (int it = 0; it < 4; it++) {
        int c  = tid + it * 256;
        int r  = c >> 3, cc = c & 7;
        cp16(baseB + (uint32_t)(r * AS + cc * 4) * 4u, wp + (size_t)r * DIM + cc * 4);
    }
}

__global__ void __launch_bounds__(256, 1)
gemm_tf32_kernel(const float* __restrict__ x, const float* __restrict__ bias,
                 float* __restrict__ out) {
    extern __shared__ float smem[];
    uint32_t sb = smem_u32(smem);

    const int tid = threadIdx.x;
    const int wid = tid >> 5, lane = tid & 31;
    const int wm = wid >> 1, wn = wid & 1;
    const int qr = lane >> 2, qc = lane & 3;
    const int mbase = blockIdx.x * BM;
    const int nbase = blockIdx.y * BN;

    float acc[4][8][4];
#pragma unroll
    for (int mi = 0; mi < 4; mi++)
#pragma unroll
        for (int ni = 0; ni < 8; ni++)
#pragma unroll
            for (int q = 0; q < 4; q++) acc[mi][ni][q] = 0.f;

    load_stage(sb, 0, 0, x, mbase, nbase, tid);
    asm volatile("cp.async.commit_group;" ::: "memory");
    load_stage(sb, 1, 1, x, mbase, nbase, tid);
    asm volatile("cp.async.commit_group;" ::: "memory");

#pragma unroll 1
    for (int i = 0; i < NKCH; i++) {
        if (i >= NKCH - 1) asm volatile("cp.async.wait_group 0;" ::: "memory");
        else               asm volatile("cp.async.wait_group 1;" ::: "memory");
        __syncthreads();

        if (i + 2 < NKCH) {
            load_stage(sb, (i + 2) % DEPTH, i + 2, x, mbase, nbase, tid);
            asm volatile("cp.async.commit_group;" ::: "memory");
        }

        const int slot = i % DEPTH;
        const uint32_t* As = (const uint32_t*)(smem + slot * STAGE_FLOATS);
        const uint32_t* Bs = As + A_FLOATS;

#pragma unroll
        for (int ks = 0; ks < 4; ks++) {
            const int kb = ks * 8;
            uint32_t a[4][4];
#pragma unroll
            for (int mi = 0; mi < 4; mi++) {
                int row = wm * 64 + mi * 16 + qr;
                a[mi][0] = As[row * AS + kb + qc];
                a[mi][1] = As[(row + 8) * AS + kb + qc];
                a[mi][2] = As[row * AS + kb + qc + 4];
                a[mi][3] = As[(row + 8) * AS + kb + qc + 4];
            }
            uint32_t b[8][2];
#pragma unroll
            for (int ni = 0; ni < 8; ni++) {
                int col = wn * 64 + ni * 8 + qr;
                b[ni][0] = Bs[col * AS + kb + qc];
                b[ni][1] = Bs[col * AS + kb + qc + 4];
            }
#pragma unroll
            for (int mi = 0; mi < 4; mi++)
#pragma unroll
                for (int ni = 0; ni < 8; ni++)
                    mma_tf32(acc[mi][ni][0], acc[mi][ni][1],
                             acc[mi][ni][2], acc[mi][ni][3],
                             a[mi][0], a[mi][1], a[mi][2], a[mi][3],
                             b[ni][0], b[ni][1]);
        }
    }

#pragma unroll
    for (int mi = 0; mi < 4; mi++) {
        int row0 = mbase + wm * 64 + mi * 16 + qr;
#pragma unroll
        for (int ni = 0; ni < 8; ni++) {
            int col = nbase + wn * 64 + ni * 8 + 2 * qc;
            float bx = bias[col], by = bias[col + 1];
            float2 v0 = make_float2(acc[mi][ni][0] + bx, acc[mi][ni][1] + by);
            float2 v1 = make_float2(acc[mi][ni][2] + bx, acc[mi][ni][3] + by);
            *(float2*)(out + (size_t)row0 * FEAT + col)       = v0;
            *(float2*)(out + (size_t)(row0 + 8) * FEAT + col) = v1;
        }
    }
}

// ============================================================================
// Kernel 3 (L1): rv[n] = x[n] . A[id[n]].  4 CTAs/adapter, 1 token/warp
//   (~70 regs -> no spills at occupancy 2).
//   A^T smem: A_sT[r][d], stride 1032 -> bank (8r+lane)%32, conflict-free.
// ============================================================================
static constexpr int ATS = DIM + 8;                            // 1032
static constexpr int L1_SMEM = 16 * ATS * 4 + 2048 * 4 + 64;   // ~74 KB

__global__ void __launch_bounds__(256, 2)
lora_rv_kernel(const float* __restrict__ x, const int* __restrict__ ids,
               const float* __restrict__ lora_a) {
    extern __shared__ char dsm[];
    float* A_sT = (float*)dsm;              // [16][ATS]
    int*   list = (int*)(A_sT + 16 * ATS);  // [2048]
    int*   cnt  = list + 2048;

    const int tid  = threadIdx.x;
    const int warp = tid >> 5, lane = tid & 31;
    const int slot = blockIdx.x >> 2;
    const int sub  = blockIdx.x & 3;

    if (tid == 0) *cnt = 0;

    {   // A[slot] (d-major 1024x16) -> A_sT[r][d]
        const float* ap = lora_a + (size_t)slot * DIM * 16;
        for (int i = tid; i < DIM * 16; i += 256) {
            int d = i >> 4, r = i & 15;
            A_sT[r * ATS + d] = ap[i];
        }
    }
    __syncthreads();

    for (int m = tid; m < N_TOK / 4; m += 256) {
        int n = 4 * m + sub;
        if (ids[n] == slot) list[atomicAdd(cnt, 1)] = n;
    }
    __syncthreads();
    const int total = *cnt;

    for (int i = warp; i < total; i += 8) {
        const int n = list[i];
        const float* xr = x + (size_t)n * DIM;

        float xv[32];
#pragma unroll
        for (int k = 0; k < 32; k++) xv[k] = xr[k * 32 + lane];

        float acc[16];
#pragma unroll
        for (int r = 0; r < 16; r++) acc[r] = 0.f;
#pragma unroll
        for (int k = 0; k < 32; k++) {
            const int d = k * 32 + lane;
            const float xd = xv[k];
#pragma unroll
            for (int r = 0; r < 16; r++)
                acc[r] = fmaf(xd, A_sT[r * ATS + d], acc[r]);
        }
#pragma unroll
        for (int r = 0; r < 16; r++) {
#pragma unroll
            for (int o = 16; o > 0; o >>= 1)
                acc[r] += __shfl_xor_sync(0xFFFFFFFFu, acc[r], o);
        }
        if (lane == 0) {
            float4* rv4 = (float4*)(g_rv + (size_t)n * 16);
            rv4[0] = make_float4(acc[0],  acc[1],  acc[2],  acc[3]);
            rv4[1] = make_float4(acc[4],  acc[5],  acc[6],  acc[7]);
            rv4[2] = make_float4(acc[8],  acc[9],  acc[10], acc[11]);
            rv4[3] = make_float4(acc[12], acc[13], acc[14], acc[15]);
        }
    }
}

// ============================================================================
// Kernel 4 (L2): out[n] += rv[n] . B[id[n]].  Token-major streaming.
// ============================================================================
__global__ void __launch_bounds__(256)
lora_out_kernel(const int* __restrict__ ids, const float* __restrict__ lora_b,
                float* __restrict__ out) {
    const int warp = threadIdx.x >> 5, lane = threadIdx.x & 31;
    const int n = blockIdx.x * 8 + warp;
    const int id = __ldg(ids + n);

    const float* rvp = g_rv + (size_t)n * 16;
    float rv[16];
#pragma unroll
    for (int r = 0; r < 16; r++) rv[r] = __ldg(rvp + r);

    const float4* B4 = (const float4*)(lora_b + (size_t)id * 16 * FEAT);
    float4* o4 = (float4*)(out + (size_t)n * FEAT);

#pragma unroll
    for (int j = 0; j < 8; j++) {
        const int f4 = j * 32 + lane;
        float4 v = o4[f4];
#pragma unroll
        for (int r = 0; r < 16; r++) {
            float4 b = __ldg(B4 + r * 256 + f4);
            v.x = fmaf(rv[r], b.x, v.x);
            v.y = fmaf(rv[r], b.y, v.y);
            v.z = fmaf(rv[r], b.z, v.z);
            v.w = fmaf(rv[r], b.w, v.w);
        }
        o4[f4] = v;
    }
}

// ============================================================================
// Launch
// ============================================================================
extern "C" void kernel_launch(void* const* d_in, const int* in_sizes, int n_in,
                              void* d_out, int out_size) {
    const float* x      = (const float*)d_in[0];
    const int*   ids    = (const int*)d_in[1];
    const float* W      = (const float*)d_in[2];
    const float* bias   = (const float*)d_in[3];
    const float* lora_a = (const float*)d_in[4];
    const float* lora_b = (const float*)d_in[5];
    float* out = (float*)d_out;

    cudaFuncSetAttribute(gemm_tf32_kernel,
                         cudaFuncAttributeMaxDynamicSharedMemorySize, GEMM_SMEM);
    cudaFuncSetAttribute(lora_rv_kernel,
                         cudaFuncAttributeMaxDynamicSharedMemorySize, L1_SMEM);

    dim3 tgrid(FEAT / 32, DIM / 32);
    transpose_w_kernel<<<tgrid, dim3(32, 8)>>>(W);

    lora_rv_kernel<<<256, 256, L1_SMEM>>>(x, ids, lora_a);

    dim3 ggrid(N_TOK / BM, FEAT / BN);   // 32 x 8
    gemm_tf32_kernel<<<ggrid, 256, GEMM_SMEM>>>(x, bias, out);

    lora_out_kernel<<<1024, 256>>>(ids, lora_b, out);
}

// round 15
// speedup vs baseline: 1.6692x; 1.6692x over previous
#include <cuda_runtime.h>
#include <cstdint>

// ============================================================================
// LoRADense: out = x @ W + bias + (x . A[id]) . B[id]
//   x:(8192,1024)f32  ids:(8192,)i32  W:(1024,1024)f32  bias:(1024,)f32
//   lora_a:(64,1024,16)f32  lora_b:(64,16,1024)f32
//
// R15: L1 rebuilt TOKEN-MAJOR register-only (mirrors L2's measured-34.7us
// pattern): warp-per-token, coalesced A[id] stream from L2, shfl-distributed
// x values, 3-level butterfly. No smem/lists/atomics.
//   GEMM: cp.async mma.sync tf32 (~65us) — unchanged
//   L2: token-major streaming (34.7us measured) — unchanged
// ============================================================================

#define N_TOK 8192
#define DIM   1024
#define FEAT  1024

__device__ float g_wt[FEAT * DIM];     // W^T tf32-rounded (4 MB)
__device__ float g_rv[N_TOK * 16];     // low-rank intermediate (512 KB)

__device__ __forceinline__ uint32_t to_tf32(float v) {
    uint32_t o;
    asm("cvt.rna.tf32.f32 %0, %1;" : "=r"(o) : "f"(v));
    return o;
}
__device__ __forceinline__ void cp16(uint32_t dst, const void* src) {
    asm volatile("cp.async.cg.shared.global [%0], [%1], 16;" :: "r"(dst), "l"(src));
}
__device__ __forceinline__ uint32_t smem_u32(const void* p) {
    uint32_t a;
    asm("{ .reg .u64 t; cvta.to.shared.u64 t, %1; cvt.u32.u64 %0, t; }"
        : "=r"(a) : "l"(p));
    return a;
}
__device__ __forceinline__ void mma_tf32(float& c0, float& c1, float& c2, float& c3,
                                         uint32_t a0, uint32_t a1, uint32_t a2, uint32_t a3,
                                         uint32_t b0, uint32_t b1) {
    asm volatile(
        "mma.sync.aligned.m16n8k8.row.col.f32.tf32.tf32.f32 "
        "{%0,%1,%2,%3}, {%4,%5,%6,%7}, {%8,%9}, {%0,%1,%2,%3};"
        : "+f"(c0), "+f"(c1), "+f"(c2), "+f"(c3)
        : "r"(a0), "r"(a1), "r"(a2), "r"(a3), "r"(b0), "r"(b1));
}

// ============================================================================
// Kernel 1: W (D,F) -> g_wt (F,D), tf32-rounded
// ============================================================================
__global__ void transpose_w_kernel(const float* __restrict__ W) {
    __shared__ float t[32][33];
    int fx = blockIdx.x * 32 + threadIdx.x;
    int dy = blockIdx.y * 32 + threadIdx.y;
#pragma unroll
    for (int i = 0; i < 32; i += 8)
        t[threadIdx.y + i][threadIdx.x] = W[(size_t)(dy + i) * FEAT + fx];
    __syncthreads();
    int dx = blockIdx.y * 32 + threadIdx.x;
    int fy = blockIdx.x * 32 + threadIdx.y;
#pragma unroll
    for (int i = 0; i < 32; i += 8)
        g_wt[(size_t)(fy + i) * DIM + dx] =
            __uint_as_float(to_tf32(t[threadIdx.x][threadIdx.y + i]));
}

// ============================================================================
// Kernel 2: tf32 GEMM, BM=256 BN=128 BK=32, 256 thr, 64x64 warp tiles
// ============================================================================
static constexpr int BM = 256, BN = 128, BK = 32;
static constexpr int AS = 36;
static constexpr int NKCH = DIM / BK;
static constexpr int DEPTH = 3;
static constexpr int A_FLOATS = BM * AS;
static constexpr int B_FLOATS = BN * AS;
static constexpr int STAGE_FLOATS = A_FLOATS + B_FLOATS;
static constexpr int GEMM_SMEM = DEPTH * STAGE_FLOATS * 4;   // 165888 B

__device__ __forceinline__ void load_stage(uint32_t sb, int slot, int kc,
                                           const float* __restrict__ x,
                                           int mbase, int nbase, int tid) {
    uint32_t baseA = sb + (uint32_t)(slot * STAGE_FLOATS) * 4u;
    uint32_t baseB = baseA + (uint32_t)A_FLOATS * 4u;
    const float* xp = x    + (size_t)mbase * DIM + kc * BK;
    const float* wp = g_wt + (size_t)nbase * DIM + kc * BK;
#pragma unroll
    for (int it = 0; it < 8; it++) {
        int c  = tid + it * 256;
        int r  = c >> 3, cc = c & 7;
        cp16(baseA + (uint32_t)(r * AS + cc * 4) * 4u, xp + (size_t)r * DIM + cc * 4);
    }
#pragma unroll
    for (int it = 0; it < 4; it++) {
        int c  = tid + it * 256;
        int r  = c >> 3, cc = c & 7;
        cp16(baseB + (uint32_t)(r * AS + cc * 4) * 4u, wp + (size_t)r * DIM + cc * 4);
    }
}

__global__ void __launch_bounds__(256, 1)
gemm_tf32_kernel(const float* __restrict__ x, const float* __restrict__ bias,
                 float* __restrict__ out) {
    extern __shared__ float smem[];
    uint32_t sb = smem_u32(smem);

    const int tid = threadIdx.x;
    const int wid = tid >> 5, lane = tid & 31;
    const int wm = wid >> 1, wn = wid & 1;
    const int qr = lane >> 2, qc = lane & 3;
    const int mbase = blockIdx.x * BM;
    const int nbase = blockIdx.y * BN;

    float acc[4][8][4];
#pragma unroll
    for (int mi = 0; mi < 4; mi++)
#pragma unroll
        for (int ni = 0; ni < 8; ni++)
#pragma unroll
            for (int q = 0; q < 4; q++) acc[mi][ni][q] = 0.f;

    load_stage(sb, 0, 0, x, mbase, nbase, tid);
    asm volatile("cp.async.commit_group;" ::: "memory");
    load_stage(sb, 1, 1, x, mbase, nbase, tid);
    asm volatile("cp.async.commit_group;" ::: "memory");

#pragma unroll 1
    for (int i = 0; i < NKCH; i++) {
        if (i >= NKCH - 1) asm volatile("cp.async.wait_group 0;" ::: "memory");
        else               asm volatile("cp.async.wait_group 1;" ::: "memory");
        __syncthreads();

        if (i + 2 < NKCH) {
            load_stage(sb, (i + 2) % DEPTH, i + 2, x, mbase, nbase, tid);
            asm volatile("cp.async.commit_group;" ::: "memory");
        }

        const int slot = i % DEPTH;
        const uint32_t* As = (const uint32_t*)(smem + slot * STAGE_FLOATS);
        const uint32_t* Bs = As + A_FLOATS;

#pragma unroll
        for (int ks = 0; ks < 4; ks++) {
            const int kb = ks * 8;
            uint32_t a[4][4];
#pragma unroll
            for (int mi = 0; mi < 4; mi++) {
                int row = wm * 64 + mi * 16 + qr;
                a[mi][0] = As[row * AS + kb + qc];
                a[mi][1] = As[(row + 8) * AS + kb + qc];
                a[mi][2] = As[row * AS + kb + qc + 4];
                a[mi][3] = As[(row + 8) * AS + kb + qc + 4];
            }
            uint32_t b[8][2];
#pragma unroll
            for (int ni = 0; ni < 8; ni++) {
                int col = wn * 64 + ni * 8 + qr;
                b[ni][0] = Bs[col * AS + kb + qc];
                b[ni][1] = Bs[col * AS + kb + qc + 4];
            }
#pragma unroll
            for (int mi = 0; mi < 4; mi++)
#pragma unroll
                for (int ni = 0; ni < 8; ni++)
                    mma_tf32(acc[mi][ni][0], acc[mi][ni][1],
                             acc[mi][ni][2], acc[mi][ni][3],
                             a[mi][0], a[mi][1], a[mi][2], a[mi][3],
                             b[ni][0], b[ni][1]);
        }
    }

#pragma unroll
    for (int mi = 0; mi < 4; mi++) {
        int row0 = mbase + wm * 64 + mi * 16 + qr;
#pragma unroll
        for (int ni = 0; ni < 8; ni++) {
            int col = nbase + wn * 64 + ni * 8 + 2 * qc;
            float bx = bias[col], by = bias[col + 1];
            float2 v0 = make_float2(acc[mi][ni][0] + bx, acc[mi][ni][1] + by);
            float2 v1 = make_float2(acc[mi][ni][2] + bx, acc[mi][ni][3] + by);
            *(float2*)(out + (size_t)row0 * FEAT + col)       = v0;
            *(float2*)(out + (size_t)(row0 + 8) * FEAT + col) = v1;
        }
    }
}

// ============================================================================
// Kernel 3 (L1): rv[n] = x[n] . A[id[n]].  TOKEN-MAJOR, register-only.
//   Warp per token. Lane (q=lane&3, h=lane>>2) reads quad q of A-row
//   d = step*8+h (warp load = 512B consecutive, fully coalesced).
//   xd comes from shfl.idx out of the xv register file:
//     d = 32*(step>>2) + 8*(step&3) + h  ->  xv[step>>2], src = 8*(step&3)+h.
//   Lane accumulates rv[4q..4q+3]; butterfly over h-bits (4,8,16);
//   lanes 0..3 store the 4 rv quads.
// ============================================================================
__global__ void __launch_bounds__(256)
lora_rv_kernel(const float* __restrict__ x, const int* __restrict__ ids,
               const float* __restrict__ lora_a) {
    const int warp = threadIdx.x >> 5, lane = threadIdx.x & 31;
    const int n = blockIdx.x * 8 + warp;
    const int id = __ldg(ids + n);
    const int q = lane & 3, h = lane >> 2;

    const float* xr = x + (size_t)n * DIM;
    float xv[32];
#pragma unroll
    for (int k = 0; k < 32; k++) xv[k] = __ldg(xr + k * 32 + lane);

    const float4* A4 = (const float4*)(lora_a + (size_t)id * DIM * 16);
    float a0 = 0.f, a1 = 0.f, a2 = 0.f, a3 = 0.f;
#pragma unroll
    for (int step = 0; step < 128; step++) {
        float4 av = __ldg(A4 + (step * 8 + h) * 4 + q);
        float xd = __shfl_sync(0xFFFFFFFFu, xv[step >> 2], ((step & 3) << 3) + h);
        a0 = fmaf(xd, av.x, a0);
        a1 = fmaf(xd, av.y, a1);
        a2 = fmaf(xd, av.z, a2);
        a3 = fmaf(xd, av.w, a3);
    }
#pragma unroll
    for (int o = 4; o <= 16; o <<= 1) {
        a0 += __shfl_xor_sync(0xFFFFFFFFu, a0, o);
        a1 += __shfl_xor_sync(0xFFFFFFFFu, a1, o);
        a2 += __shfl_xor_sync(0xFFFFFFFFu, a2, o);
        a3 += __shfl_xor_sync(0xFFFFFFFFu, a3, o);
    }
    if (lane < 4)
        ((float4*)(g_rv + (size_t)n * 16))[q] = make_float4(a0, a1, a2, a3);
}

// ============================================================================
// Kernel 4 (L2): out[n] += rv[n] . B[id[n]].  Token-major streaming.
// ============================================================================
__global__ void __launch_bounds__(256)
lora_out_kernel(const int* __restrict__ ids, const float* __restrict__ lora_b,
                float* __restrict__ out) {
    const int warp = threadIdx.x >> 5, lane = threadIdx.x & 31;
    const int n = blockIdx.x * 8 + warp;
    const int id = __ldg(ids + n);

    const float* rvp = g_rv + (size_t)n * 16;
    float rv[16];
#pragma unroll
    for (int r = 0; r < 16; r++) rv[r] = __ldg(rvp + r);

    const float4* B4 = (const float4*)(lora_b + (size_t)id * 16 * FEAT);
    float4* o4 = (float4*)(out + (size_t)n * FEAT);

#pragma unroll
    for (int j = 0; j < 8; j++) {
        const int f4 = j * 32 + lane;
        float4 v = o4[f4];
#pragma unroll
        for (int r = 0; r < 16; r++) {
            float4 b = __ldg(B4 + r * 256 + f4);
            v.x = fmaf(rv[r], b.x, v.x);
            v.y = fmaf(rv[r], b.y, v.y);
            v.z = fmaf(rv[r], b.z, v.z);
            v.w = fmaf(rv[r], b.w, v.w);
        }
        o4[f4] = v;
    }
}

// ============================================================================
// Launch
// ============================================================================
extern "C" void kernel_launch(void* const* d_in, const int* in_sizes, int n_in,
                              void* d_out, int out_size) {
    const float* x      = (const float*)d_in[0];
    const int*   ids    = (const int*)d_in[1];
    const float* W      = (const float*)d_in[2];
    const float* bias   = (const float*)d_in[3];
    const float* lora_a = (const float*)d_in[4];
    const float* lora_b = (const float*)d_in[5];
    float* out = (float*)d_out;

    cudaFuncSetAttribute(gemm_tf32_kernel,
                         cudaFuncAttributeMaxDynamicSharedMemorySize, GEMM_SMEM);

    dim3 tgrid(FEAT / 32, DIM / 32);
    transpose_w_kernel<<<tgrid, dim3(32, 8)>>>(W);

    lora_rv_kernel<<<1024, 256>>>(x, ids, lora_a);

    dim3 ggrid(N_TOK / BM, FEAT / BN);   // 32 x 8
    gemm_tf32_kernel<<<ggrid, 256, GEMM_SMEM>>>(x, bias, out);

    lora_out_kernel<<<1024, 256>>>(ids, lora_b, out);
}